// round 17
// baseline (speedup 1.0000x reference)
#include <cuda_runtime.h>
#include <cuda_bf16.h>
#include <math.h>
#include <stdint.h>

typedef unsigned long long ull;
#define FMA2(acc, a, b) asm("fma.rn.f32x2 %0, %1, %2, %0;" : "+l"(acc) : "l"(a), "l"(b))
__device__ __forceinline__ ull dupf(float x) { ull r; asm("mov.b64 %0, {%1, %1};" : "=l"(r) : "f"(x)); return r; }
__device__ __forceinline__ float2 u2f(ull v) { float2 r; asm("mov.b64 {%0, %1}, %2;" : "=f"(r.x), "=f"(r.y) : "l"(v)); return r; }
__device__ __forceinline__ uint32_t s2u(const void* p) {
    uint32_t a;
    asm("{.reg .u64 t; cvta.to.shared.u64 t, %1; cvt.u32.u64 %0, t;}" : "=r"(a) : "l"(p));
    return a;
}

// device-global scratch
__device__ float g_XW [(size_t)4096 * 4096];
__device__ float g_H  [(size_t)4096 * 1024];
__device__ ull   g_At [(size_t)1024 * 4096];   // k-major A, each elem duplicated (v,v)
__device__ float g_Up0[(size_t)1024 * 4096];
__device__ float g_Up1[(size_t)1024 * 4096];
__device__ float g_h  [2][16 * 1024];
// tree barrier state: 8 leaf counters (padded to separate L2 lines), root cnt, gen
__device__ unsigned g_lcnt[8 * 32];
__device__ unsigned g_rcnt;
__device__ unsigned g_gen;

// Up[k][j][g] = U[k][g*1024+j]
__global__ void repack(const float* __restrict__ U, float* __restrict__ Up) {
    int i = blockIdx.x * 256 + threadIdx.x;
    int k = i >> 10, j = i & 1023;
    float4 v = { U[(size_t)k*4096 + j],        U[(size_t)k*4096 + 1024 + j],
                 U[(size_t)k*4096 + 2048 + j], U[(size_t)k*4096 + 3072 + j] };
    ((float4*)Up)[(size_t)k*1024 + j] = v;
}

// At[k][s] = dup(emb[seq[s%16, s/16]][k] * 32)
__global__ void tX(const int* __restrict__ seq, const float* __restrict__ emb,
                   ull* __restrict__ At) {
    __shared__ float t[32][33];
    int sb = blockIdx.x * 32, kb = blockIdx.y * 32;
    int x = threadIdx.x, y = threadIdx.y;            // (32, 8)
#pragma unroll
    for (int i = 0; i < 4; i++) {
        int s = sb + y + 8 * i;
        int tok = seq[(s & 15) * 256 + (s >> 4)];
        t[y + 8*i][x] = emb[(size_t)tok * 1024 + kb + x] * 32.f;
    }
    __syncthreads();
#pragma unroll
    for (int i = 0; i < 4; i++)
        At[(size_t)(kb + y + 8*i) * 4096 + sb + x] = dupf(t[x][y + 8*i]);
}

// At[k][s] = dup(H[s][k])
__global__ void tH(const float* __restrict__ H, ull* __restrict__ At) {
    __shared__ float t[32][33];
    int sb = blockIdx.x * 32, kb = blockIdx.y * 32;
    int x = threadIdx.x, y = threadIdx.y;            // (32, 8)
#pragma unroll
    for (int i = 0; i < 4; i++)
        t[y + 8*i][x] = H[(size_t)(sb + y + 8*i) * 1024 + kb + x];
    __syncthreads();
#pragma unroll
    for (int i = 0; i < 4; i++)
        At[(size_t)(kb + y + 8*i) * 4096 + sb + x] = dupf(t[x][y + 8*i]);
}

// pipelined f32x2 GEMM: C[4096, N] = At^T @ Bm + bias, 2-stage cp.async.
// A pre-duplicated u64; inner loop = 6 conflict-free LDS.128 + 32 FMA2, 0 MOVs.
// Thread m-rows: {wm+lm*4+i} and {wm+16+lm*4+i}; B cols {wn+ln*4, wn+32+ln*4}.
// cmode1: row s -> out[(s%16)*256 + s/16] remap.
__global__ __launch_bounds__(256, 2)
void gemm2(const ull* __restrict__ At, const float* __restrict__ Bm,
           const float* __restrict__ bias, float* __restrict__ C,
           int N, int cmode)
{
    __shared__ ull   As[2][16][128];   // 32KB
    __shared__ float Bs[2][16][128];   // 16KB
    const int tid = threadIdx.x, lane = tid & 31, wid = tid >> 5;
    const int m0 = blockIdx.x * 128, n0 = blockIdx.y * 128;
    const int wm = (wid & 3) * 32, wn = (wid >> 2) * 64;
    const int lm = lane & 3, ln = lane >> 2;
    const int ar0 = wm + lm * 4, ar1 = wm + 16 + lm * 4;
    const int bc = wn + ln * 4;

    ull acc[8][4];
#pragma unroll
    for (int i = 0; i < 8; i++)
#pragma unroll
        for (int j = 0; j < 4; j++) acc[i][j] = 0ull;

    // A: 1024 16B-chunks/stage (4/thread); B: 512 (2/thread)
    auto issue = [&](int st, int k0) {
#pragma unroll
        for (int i = 0; i < 4; i++) {
            int c = tid + i * 256, kk = c >> 6, seg = c & 63;
            uint32_t da = s2u(&As[st][kk][seg * 2]);
            const void* sa = At + (size_t)(k0 + kk) * 4096 + m0 + seg * 2;
            asm volatile("cp.async.cg.shared.global [%0], [%1], 16;" :: "r"(da), "l"(sa));
        }
#pragma unroll
        for (int i = 0; i < 2; i++) {
            int c = tid + i * 256, kk = c >> 5, seg = c & 31;
            uint32_t db = s2u(&Bs[st][kk][seg * 4]);
            const void* sb = Bm + (size_t)(k0 + kk) * N + n0 + seg * 4;
            asm volatile("cp.async.cg.shared.global [%0], [%1], 16;" :: "r"(db), "l"(sb));
        }
        asm volatile("cp.async.commit_group;");
    };

    issue(0, 0);
    for (int it = 0; it < 64; it++) {
        if (it < 63) {
            issue((it + 1) & 1, (it + 1) * 16);
            asm volatile("cp.async.wait_group 1;");
        } else {
            asm volatile("cp.async.wait_group 0;");
        }
        __syncthreads();
        const int st = it & 1;
#pragma unroll
        for (int kk = 0; kk < 16; kk++) {
            ull ra[8], rb[4];
            *(uint4*)&ra[0] = *(uint4*)&As[st][kk][ar0];
            *(uint4*)&ra[2] = *(uint4*)&As[st][kk][ar0 + 2];
            *(uint4*)&ra[4] = *(uint4*)&As[st][kk][ar1];
            *(uint4*)&ra[6] = *(uint4*)&As[st][kk][ar1 + 2];
            float4 b0_ = *(float4*)&Bs[st][kk][bc];
            float4 b1_ = *(float4*)&Bs[st][kk][bc + 32];
            rb[0] = ((ull*)&b0_)[0]; rb[1] = ((ull*)&b0_)[1];
            rb[2] = ((ull*)&b1_)[0]; rb[3] = ((ull*)&b1_)[1];
#pragma unroll
            for (int i = 0; i < 8; i++) {
                FMA2(acc[i][0], ra[i], rb[0]); FMA2(acc[i][1], ra[i], rb[1]);
                FMA2(acc[i][2], ra[i], rb[2]); FMA2(acc[i][3], ra[i], rb[3]);
            }
        }
        __syncthreads();
    }
    float bi0[4], bi1[4];
#pragma unroll
    for (int j = 0; j < 4; j++) {
        bi0[j] = bias[n0 + bc + j];
        bi1[j] = bias[n0 + bc + 32 + j];
    }
#pragma unroll
    for (int i = 0; i < 8; i++) {
        int s = m0 + ((i < 4) ? (ar0 + i) : (ar1 + i - 4));
        size_t base = cmode
            ? (size_t)(s & 15) * 8192000u + (size_t)(s >> 4) * 32000u
            : (size_t)s * N;
        float2 v0 = u2f(acc[i][0]), v1 = u2f(acc[i][1]);
        float2 v2 = u2f(acc[i][2]), v3 = u2f(acc[i][3]);
        float4 c0 = { v0.x + bi0[0], v0.y + bi0[1], v1.x + bi0[2], v1.y + bi0[3] };
        float4 c1 = { v2.x + bi1[0], v2.y + bi1[1], v3.x + bi1[2], v3.y + bi1[3] };
        *(float4*)(C + base + n0 + bc)      = c0;
        *(float4*)(C + base + n0 + bc + 32) = c1;
    }
}

// two-level tree grid barrier: 8 leaves x 16 blocks -> root -> gen flip
__device__ __forceinline__ void gbar() {
    __syncthreads();
    if (threadIdx.x == 0) {
        const int lf = (blockIdx.x >> 4) * 32;
        unsigned gen, a;
        asm volatile("ld.acquire.gpu.global.u32 %0, [%1];" : "=r"(gen) : "l"(&g_gen));
        asm volatile("atom.acq_rel.gpu.global.add.u32 %0, [%1], %2;"
                     : "=r"(a) : "l"(&g_lcnt[lf]), "r"(1u));
        if (a == 15u) {
            unsigned r;
            asm volatile("atom.acq_rel.gpu.global.add.u32 %0, [%1], %2;"
                         : "=r"(r) : "l"(&g_rcnt), "r"(1u));
            if (r == 7u) {
#pragma unroll
                for (int i = 0; i < 8; i++)
                    asm volatile("st.relaxed.gpu.global.u32 [%0], %1;"
                                 :: "l"(&g_lcnt[i * 32]), "r"(0u));
                asm volatile("st.relaxed.gpu.global.u32 [%0], %1;" :: "l"(&g_rcnt), "r"(0u));
                asm volatile("red.release.gpu.global.add.u32 [%0], %1;"
                             :: "l"(&g_gen), "r"(1u));
            }
        }
        unsigned c;
        do { asm volatile("ld.acquire.gpu.global.u32 %0, [%1];" : "=r"(c) : "l"(&g_gen)); }
        while (c == gen);
    }
    __syncthreads();
}

// fused persistent LSTM layer (proven structure; tree barrier)
#define SM_UP 0
#define SM_HS 131072
#define SM_RED (131072 + 81920)
#define SMEM_LSTM (131072 + 81920 + 16384)
__global__ __launch_bounds__(256, 1)
void lstm_fused(const float4* __restrict__ Up, const float* __restrict__ XW,
                float* __restrict__ H)
{
    extern __shared__ char sm_[];
    float4* up_s = (float4*)(sm_ + SM_UP);
    float*  hs   = (float*) (sm_ + SM_HS);
    float4* red  = (float4*)(sm_ + SM_RED);

    const int tid = threadIdx.x, bl = blockIdx.x;
    const int w = tid >> 5, lane = tid & 31;
    const int jj = (tid & 31) >> 2, bg = tid & 3;
    const int sbB = lane >> 1, kg = lane & 1;
    const int bR = (tid & 127) >> 3, jR = tid & 7;
    const int jRg = bl * 8 + jR;

    {
        const float4* up = Up + bl * 8;
#pragma unroll 8
        for (int i = tid; i < 8192; i += 256)
            up_s[i] = up[(size_t)(i >> 3) * 1024 + (i & 7)];
    }
    if (tid < 128) g_h[0][bl * 128 + tid] = 0.f;
    float creg = 0.f;
    gbar();

    for (int t = 0; t < 256; t++) {
        float xw[4];
        if (tid < 128) {
            const float* xp = XW + (size_t)(t * 16 + bR) * 4096 + jRg;
#pragma unroll
            for (int g = 0; g < 4; g++) xw[g] = __ldcg(xp + g * 1024);
        }
        {
            const float4* hsrc = (const float4*)g_h[t & 1] + sbB * 256;
#pragma unroll
            for (int i = 0; i < 16; i++) {
                int k4 = i * 16 + w * 2 + kg;
                float4 v = __ldcg(hsrc + k4);
                float* d = hs + (k4 * 4) * 20 + sbB;
                d[0] = v.x; d[20] = v.y; d[40] = v.z; d[60] = v.w;
            }
        }
        __syncthreads();
        ull acc[4][2];
#pragma unroll
        for (int g = 0; g < 4; g++) { acc[g][0] = 0ull; acc[g][1] = 0ull; }
        const float4* up = up_s + w * 128 * 8 + jj;
        const float*  hp = hs + w * 128 * 20 + bg * 4;
#pragma unroll 8
        for (int kk = 0; kk < 128; kk++) {
            float4 u  = up[kk * 8];
            float4 hv = *(const float4*)(hp + kk * 20);
            ull h2a = ((ull*)&hv)[0], h2b = ((ull*)&hv)[1];
            ull a0 = dupf(u.x), a1 = dupf(u.y), a2 = dupf(u.z), a3 = dupf(u.w);
            FMA2(acc[0][0], a0, h2a); FMA2(acc[0][1], a0, h2b);
            FMA2(acc[1][0], a1, h2a); FMA2(acc[1][1], a1, h2b);
            FMA2(acc[2][0], a2, h2a); FMA2(acc[2][1], a2, h2b);
            FMA2(acc[3][0], a3, h2a); FMA2(acc[3][1], a3, h2b);
        }
        {
            float2 p[4][2];
#pragma unroll
            for (int g = 0; g < 4; g++) { p[g][0] = u2f(acc[g][0]); p[g][1] = u2f(acc[g][1]); }
#pragma unroll
            for (int i = 0; i < 4; i++) {
                int b = bg * 4 + i;
                float4 zv;
                zv.x = (i & 1) ? p[0][i >> 1].y : p[0][i >> 1].x;
                zv.y = (i & 1) ? p[1][i >> 1].y : p[1][i >> 1].x;
                zv.z = (i & 1) ? p[2][i >> 1].y : p[2][i >> 1].x;
                zv.w = (i & 1) ? p[3][i >> 1].y : p[3][i >> 1].x;
                red[(w * 16 + b) * 8 + jj] = zv;
            }
        }
        __syncthreads();
        if (tid < 128) {
            float z0 = xw[0], z1 = xw[1], z2 = xw[2], z3 = xw[3];
#pragma unroll
            for (int q = 0; q < 8; q++) {
                float4 r = red[(q * 16 + bR) * 8 + jR];
                z0 += r.x; z1 += r.y; z2 += r.z; z3 += r.w;
            }
            float i_ = 1.f / (1.f + expf(-z0));
            float f_ = 1.f / (1.f + expf(-z1));
            float o_ = 1.f / (1.f + expf(-z3));
            creg = f_ * creg + i_ * tanhf(z2);
            float hn = o_ * tanhf(creg);
            __stcg(&g_h[(t + 1) & 1][bR * 1024 + jRg], hn);
            __stcg(&H[(size_t)(t * 16 + bR) * 1024 + jRg], hn);
        }
        gbar();
    }
}

extern "C" void kernel_launch(void* const* d_in, const int* in_sizes, int n_in,
                              void* d_out, int out_size)
{
    const int*   seq  = (const int*)  d_in[0];
    const float* emb  = (const float*)d_in[1];
    const float* W0   = (const float*)d_in[2];
    const float* U0   = (const float*)d_in[3];
    const float* b0   = (const float*)d_in[4];
    const float* W1   = (const float*)d_in[5];
    const float* U1   = (const float*)d_in[6];
    const float* b1   = (const float*)d_in[7];
    const float* Wout = (const float*)d_in[8];
    const float* bout = (const float*)d_in[9];
    float* out = (float*)d_out;

    float *XW, *H, *Up0, *Up1;
    ull *At;
    cudaGetSymbolAddress((void**)&XW,  g_XW);
    cudaGetSymbolAddress((void**)&H,   g_H);
    cudaGetSymbolAddress((void**)&At,  g_At);
    cudaGetSymbolAddress((void**)&Up0, g_Up0);
    cudaGetSymbolAddress((void**)&Up1, g_Up1);

    cudaFuncSetAttribute(lstm_fused, cudaFuncAttributeMaxDynamicSharedMemorySize, SMEM_LSTM);

    repack<<<4096, 256>>>(U0, Up0);
    repack<<<4096, 256>>>(U1, Up1);

    tX<<<dim3(128, 32), dim3(32, 8)>>>(seq, emb, At);
    gemm2<<<dim3(32, 32), 256>>>(At, W0, b0, XW, 4096, 0);
    lstm_fused<<<128, 256, SMEM_LSTM>>>((const float4*)Up0, XW, H);

    tH<<<dim3(128, 32), dim3(32, 8)>>>(H, At);
    gemm2<<<dim3(32, 32), 256>>>(At, W1, b1, XW, 4096, 0);
    lstm_fused<<<128, 256, SMEM_LSTM>>>((const float4*)Up1, XW, H);

    tH<<<dim3(128, 32), dim3(32, 8)>>>(H, At);
    gemm2<<<dim3(32, 250), 256>>>(At, Wout, bout, out, 32000, 1);
}